// round 15
// baseline (speedup 1.0000x reference)
#include <cuda_runtime.h>
#include <stdint.h>

// Problem constants (fixed by the reference's setup_inputs)
#define NUM_GRAPHS 512
#define NPG        1024
#define KSEL       512
#define NTOT       (NUM_GRAPHS * NPG)     // 524288 nodes
#define NSEL       (NUM_GRAPHS * KSEL)    // 262144 selected
#define NEDGE      8388608                // 16 * NTOT

// Output layout (float32, concatenated reference outputs:
// x_sel [NSEL,64] | new_edge_index [2,NEDGE] | batch_sel [NSEL] | perm [NSEL])
#define X_OFF      0ll
#define EDGE_OFF   16777216ll             // NSEL * 64
#define BATCH_OFF  33554432ll             // EDGE_OFF + 2*NEDGE
#define PERM_OFF   33816576ll             // BATCH_OFF + NSEL

#define LUT_WORDS     (NTOT / 32)         // 16384
#define SMEM_BYTES    (LUT_WORDS * 4 + LUT_WORDS * 2)  // 96 KB

#define GATHER_CHUNKS 2048                // NSEL*8 threads / 1024
#define EDGE_CHUNKS   1024                // NEDGE/8 threads / 1024
#define TOTAL_CHUNKS  (GATHER_CHUNKS + EDGE_CHUNKS)

#define SEL_THREADS   512                 // select: 512 threads, 2 elems each

// Scratch (static device globals — no allocation)
__device__ int            g_perm[NSEL];
__device__ unsigned int   g_bits[LUT_WORDS];   // ballot word per 32 nodes
__device__ unsigned short g_base[LUT_WORDS];   // within-graph rank base (<=512)
__device__ int            g_is64;

__device__ __forceinline__ uint32_t rotl32(uint32_t x, int r) {
    return __funnelshift_l(x, x, r);
}

// Threefry-2x32, 20 rounds — bit-exact match of jax._src.prng.threefry2x32
__device__ __forceinline__ void threefry(uint32_t k0, uint32_t k1,
                                         uint32_t x0, uint32_t x1,
                                         uint32_t& o0, uint32_t& o1) {
    uint32_t k2 = k0 ^ k1 ^ 0x1BD11BDAu;
    x0 += k0; x1 += k1;
#define TF_R(r) { x0 += x1; x1 = rotl32(x1, (r)); x1 ^= x0; }
    TF_R(13) TF_R(15) TF_R(26) TF_R(6)   x0 += k1; x1 += k2 + 1u;
    TF_R(17) TF_R(29) TF_R(16) TF_R(24)  x0 += k2; x1 += k0 + 2u;
    TF_R(13) TF_R(15) TF_R(26) TF_R(6)   x0 += k0; x1 += k1 + 3u;
    TF_R(17) TF_R(29) TF_R(16) TF_R(24)  x0 += k1; x1 += k2 + 4u;
    TF_R(13) TF_R(15) TF_R(26) TF_R(6)   x0 += k2; x1 += k0 + 5u;
#undef TF_R
    o0 = x0; o1 = x1;
}

// One 512-thread block per graph, 2 elements per thread (e0=t, e1=t+512).
// Select = the 512 entries with smallest stable composite (key<<32|idx),
// via 1024-bucket radix select + exact tie resolution in the threshold
// bucket. Rank = prefix-popcount. 4 blocks/SM => single wave over 512 graphs.
__global__ __launch_bounds__(SEL_THREADS) void select_kernel(
    float* __restrict__ out, const unsigned int* __restrict__ e) {
    __shared__ unsigned int counts[1024];
    __shared__ unsigned int waux[32];
    __shared__ unsigned int woff[32];
    __shared__ unsigned int sThresh[2];       // [0]=T bucket, [1]=R
    __shared__ unsigned int sNT;
    __shared__ unsigned long long list[1024]; // threshold-bucket composites

    const int g = blockIdx.x;
    const int t = threadIdx.x;
    const int w = t >> 5;                     // 0..15
    const int lane = t & 31;

    // dtype sniff (int64 => odd 32-bit words all zero, ids < 2^19)
    if (g == 0 && w == 0) {
        unsigned int v = e[2 * lane + 1] | e[2 * (lane + 32) + 1];
        unsigned int any = __ballot_sync(0xFFFFFFFFu, v != 0u);
        if (lane == 0) g_is64 = (any == 0u) ? 1 : 0;
    }

    // Per-graph keys: key_g = threefry((0,42),(0,g)); subkey = threefry(key_g,(0,1))
    uint32_t a0, a1, b0, b1;
    threefry(0u, 42u, 0u, (uint32_t)g, a0, a1);
    threefry(a0, a1, 0u, 1u, b0, b1);

    const int eA = t;            // element 0
    const int eB = t + 512;      // element 1
    uint32_t cA0, cA1, cB0, cB1;
    threefry(b0, b1, 0u, (uint32_t)eA, cA0, cA1);
    threefry(b0, b1, 0u, (uint32_t)eB, cB0, cB1);
    const uint32_t skA = cA0 ^ cA1;
    const uint32_t skB = cB0 ^ cB1;
    const unsigned long long keyA =
        ((unsigned long long)skA << 32) | (unsigned long long)eA;
    const unsigned long long keyB =
        ((unsigned long long)skB << 32) | (unsigned long long)eB;
    const unsigned int bkA = skA >> 22;
    const unsigned int bkB = skB >> 22;

    counts[2 * t] = 0;
    counts[2 * t + 1] = 0;
    if (t == 0) sNT = 0;
    __syncthreads();
    atomicAdd(&counts[bkA], 1u);
    atomicAdd(&counts[bkB], 1u);
    __syncthreads();

    // Exclusive scan over counts[1024]: each thread owns pair (2t, 2t+1)
    {
        const unsigned int v0 = counts[2 * t];
        const unsigned int v1 = counts[2 * t + 1];
        const unsigned int s = v0 + v1;
        unsigned int inc = s;
#pragma unroll
        for (int d = 1; d < 32; d <<= 1) {
            unsigned int n_ = __shfl_up_sync(0xFFFFFFFFu, inc, d);
            if (lane >= d) inc += n_;
        }
        if (lane == 31) waux[w] = inc;        // 16 warp totals
        __syncthreads();
        if (w == 0 && lane < 16) {
            unsigned int sv = waux[lane];
            unsigned int si = sv;
#pragma unroll
            for (int d = 1; d < 16; d <<= 1) {
                unsigned int n_ = __shfl_up_sync(0x0000FFFFu, si, d);
                if (lane >= d) si += n_;
            }
            woff[lane] = si - sv;             // exclusive warp offsets
        }
        __syncthreads();
        const unsigned int exPair = woff[w] + inc - s;  // excl for 2t
        const unsigned int ex0 = exPair;
        const unsigned int ex1 = exPair + v0;
        if (ex0 <= 511u && 511u < ex0 + v0) {
            sThresh[0] = (unsigned int)(2 * t);
            sThresh[1] = 512u - ex0;
        }
        if (ex1 <= 511u && 511u < ex1 + v1) {
            sThresh[0] = (unsigned int)(2 * t + 1);
            sThresh[1] = 512u - ex1;
        }
    }
    __syncthreads();
    const unsigned int T = sThresh[0];
    const unsigned int R = sThresh[1];

    // Compact threshold-bucket composites, then exact rank-compare
    if (bkA == T) { unsigned int pos = atomicAdd(&sNT, 1u); list[pos] = keyA; }
    if (bkB == T) { unsigned int pos = atomicAdd(&sNT, 1u); list[pos] = keyB; }
    __syncthreads();
    const unsigned int nT = sNT;
    bool selA, selB;
    if (bkA < T) selA = true;
    else if (bkA > T) selA = false;
    else {
        unsigned int rank = 0;
        for (unsigned int jj = 0; jj < nT; jj++)
            rank += (list[jj] < keyA) ? 1u : 0u;
        selA = (rank < R);
    }
    if (bkB < T) selB = true;
    else if (bkB > T) selB = false;
    else {
        unsigned int rank = 0;
        for (unsigned int jj = 0; jj < nT; jj++)
            rank += (list[jj] < keyB) ? 1u : 0u;
        selB = (rank < R);
    }

    // Ballot ranks: element words — eA covers words [0,16), eB words [16,32)
    const unsigned int wordA = __ballot_sync(0xFFFFFFFFu, selA);
    const unsigned int wordB = __ballot_sync(0xFFFFFFFFu, selB);
    if (lane == 0) {
        waux[w] = __popc(wordA);
        waux[16 + w] = __popc(wordB);
    }
    __syncthreads();
    if (w == 0) {                              // scan all 32 word counts
        unsigned int sv = waux[lane];
        unsigned int si = sv;
#pragma unroll
        for (int d = 1; d < 32; d <<= 1) {
            unsigned int n_ = __shfl_up_sync(0xFFFFFFFFu, si, d);
            if (lane >= d) si += n_;
        }
        woff[lane] = si - sv;
    }
    __syncthreads();

    const unsigned int baseA = woff[w];        // within-graph, <=512
    const unsigned int baseB = woff[16 + w];
    if (lane == 0) {
        g_bits[g * 32 + w]      = wordA;
        g_base[g * 32 + w]      = (unsigned short)baseA;
        g_bits[g * 32 + 16 + w] = wordB;
        g_base[g * 32 + 16 + w] = (unsigned short)baseB;
    }
    if (selA) {
        const int rank = g * KSEL + (int)baseA + __popc(wordA & ((1u << lane) - 1u));
        const int global = g * NPG + eA;
        g_perm[rank] = global;
        out[BATCH_OFF + rank] = (float)g;
        out[PERM_OFF  + rank] = (float)global;
    }
    if (selB) {
        const int rank = g * KSEL + (int)baseB + __popc(wordB & ((1u << lane) - 1u));
        const int global = g * NPG + eB;
        g_perm[rank] = global;
        out[BATCH_OFF + rank] = (float)g;
        out[PERM_OFF  + rank] = (float)global;
    }
}

// Relabel node id via shared-memory packed LUT:
// global rank = (n>>10)*512 + base16[n>>5] + popc(bits & below-lane mask)
__device__ __forceinline__ int relabel_s(const unsigned int* __restrict__ sbits,
                                         const unsigned short* __restrict__ sbase,
                                         unsigned int n) {
    if (n >= NTOT) return -1;
    const unsigned int wi = n >> 5;
    const unsigned int W = sbits[wi];
    const unsigned int b = n & 31u;
    if (!((W >> b) & 1u)) return -1;
    return (int)((n >> 10) * KSEL + (unsigned int)sbase[wi]
                 + __popc(W & ((1u << b) - 1u)));
}

// Chunk bodies (identical logic to R14 inline code)
__device__ __forceinline__ void do_gather(int gb, int tidc,
                                          const float4* __restrict__ x,
                                          float4* __restrict__ xout) {
    const int i = gb * 1024 + tidc;                  // 0 .. NSEL*8-1
    const int row = i >> 3;
    const int cc = i & 7;
    const long long src = (long long)__ldg(&g_perm[row]) * 16;
    const long long dst = (long long)row * 16;
    const float4 v0 = __ldcs(&x[src + cc]);
    const float4 v1 = __ldcs(&x[src + cc + 8]);
    __stcs(&xout[dst + cc],     v0);
    __stcs(&xout[dst + cc + 8], v1);
}

__device__ __forceinline__ void do_edge(int eb, int tidc, bool is64,
                                        const unsigned int* __restrict__ eidx,
                                        const unsigned int* __restrict__ sbits,
                                        const unsigned short* __restrict__ sbase,
                                        float4* __restrict__ outr,
                                        float4* __restrict__ outc) {
    const int j = eb * 1024 + tidc;
    const int e0 = j * 8;                            // 8 edges per thread
    int n[8], m[8];
    const int4* p = (const int4*)eidx;
    if (is64) {
        const int4* q = p + (NEDGE / 2);
        int4 A[4], B[4];
#pragma unroll
        for (int k = 0; k < 4; k++) {
            A[k] = __ldcs(&p[e0 / 2 + k]);
            B[k] = __ldcs(&q[e0 / 2 + k]);
        }
#pragma unroll
        for (int k = 0; k < 4; k++) {
            n[2 * k] = A[k].x; n[2 * k + 1] = A[k].z;
            m[2 * k] = B[k].x; m[2 * k + 1] = B[k].z;
        }
    } else {
        const int4* q = p + (NEDGE / 4);
        int4 A0 = __ldcs(&p[e0 / 4]), A1 = __ldcs(&p[e0 / 4 + 1]);
        int4 B0 = __ldcs(&q[e0 / 4]), B1 = __ldcs(&q[e0 / 4 + 1]);
        n[0] = A0.x; n[1] = A0.y; n[2] = A0.z; n[3] = A0.w;
        n[4] = A1.x; n[5] = A1.y; n[6] = A1.z; n[7] = A1.w;
        m[0] = B0.x; m[1] = B0.y; m[2] = B0.z; m[3] = B0.w;
        m[4] = B1.x; m[5] = B1.y; m[6] = B1.z; m[7] = B1.w;
    }
    float rr[8], cc2[8];
#pragma unroll
    for (int k = 0; k < 8; k++) {
        const int r  = relabel_s(sbits, sbase, (unsigned int)n[k]);
        const int cl = relabel_s(sbits, sbase, (unsigned int)m[k]);
        const bool keep = (r >= 0) & (cl >= 0);
        rr[k]  = keep ? (float)r  : -1.0f;
        cc2[k] = keep ? (float)cl : -1.0f;
    }
    __stcs(&outr[e0 / 4],     make_float4(rr[0], rr[1], rr[2], rr[3]));
    __stcs(&outr[e0 / 4 + 1], make_float4(rr[4], rr[5], rr[6], rr[7]));
    __stcs(&outc[e0 / 4],     make_float4(cc2[0], cc2[1], cc2[2], cc2[3]));
    __stcs(&outc[e0 / 4 + 1], make_float4(cc2[4], cc2[5], cc2[6], cc2[7]));
}

__device__ __forceinline__ void do_chunk(unsigned int c, int tidc, bool is64,
                                         const float4* __restrict__ x,
                                         const unsigned int* __restrict__ eidx,
                                         const unsigned int* __restrict__ sbits,
                                         const unsigned short* __restrict__ sbase,
                                         float4* __restrict__ xout,
                                         float4* __restrict__ outr,
                                         float4* __restrict__ outc) {
    const unsigned int phase = c % 3u;               // 0,1 => gather; 2 => edge
    if (phase != 2u) {
        do_gather((int)(c / 3u) * 2 + (int)phase, tidc, x, xout);
    } else {
        do_edge((int)(c / 3u), tidc, is64, eidx, sbits, sbase, outr, outc);
    }
}

// Persistent stream kernel, 2 blocks/SM (96KB smem each): stage packed LUT,
// then process 3072 chunks interleaved 2 gather : 1 edge.
// Remainder smoothing: TOTAL_CHUNKS mod grid chunks are spread across ALL
// blocks at unit granularity (bijective u -> (chunk, tid-in-chunk) map), so
// every block does the same total work (no 1-chunk tail on 32 blocks).
__global__ __launch_bounds__(1024, 2) void stream_kernel(
    const float4* __restrict__ x,
    const unsigned int* __restrict__ eidx,
    float4* __restrict__ xout,
    float4* __restrict__ outr,
    float4* __restrict__ outc) {
    extern __shared__ unsigned int dyn[];
    unsigned int* sbits = dyn;                                  // 64 KB
    unsigned short* sbase = (unsigned short*)(dyn + LUT_WORDS); // 32 KB

    // Stage LUT (bits: 4096 uint4; base: 2048 uint4)
    {
        const uint4* src = (const uint4*)g_bits;
        uint4* dst = (uint4*)sbits;
#pragma unroll
        for (int k = 0; k < 4; k++)
            dst[k * 1024 + threadIdx.x] = __ldg(&src[k * 1024 + threadIdx.x]);
        const uint4* src2 = (const uint4*)g_base;
        uint4* dst2 = (uint4*)sbase;
#pragma unroll
        for (int k = 0; k < 2; k++)
            dst2[k * 1024 + threadIdx.x] = __ldg(&src2[k * 1024 + threadIdx.x]);
    }
    __syncthreads();

    const int tid = threadIdx.x;
    const bool is64 = (g_is64 != 0);

    const unsigned int G = gridDim.x;
    const unsigned int even = (TOTAL_CHUNKS / G) * G;
    const unsigned int rem = TOTAL_CHUNKS - even;    // < G

    // Remainder pre-pass: rem*1024 units spread across all blocks
    if (rem != 0u) {
        const unsigned int u = blockIdx.x * 1024u + (unsigned int)tid;
        const unsigned int remUnits = rem * 1024u;
        if (u < remUnits) {
            const unsigned int c = even + (u % rem);
            const int tidc = (int)(u / rem);
            do_chunk(c, tidc, is64, x, eidx, sbits, sbase, xout, outr, outc);
        }
    }

    // Even part: exactly TOTAL_CHUNKS/G chunks per block
    for (unsigned int c = blockIdx.x; c < even; c += G)
        do_chunk(c, tid, is64, x, eidx, sbits, sbase, xout, outr, outc);
}

extern "C" void kernel_launch(void* const* d_in, const int* in_sizes, int n_in,
                              void* d_out, int out_size) {
    const float* x        = (const float*)d_in[0];
    const unsigned int* e = (const unsigned int*)d_in[1];
    float* out            = (float*)d_out;

    static int grid = 0;
    if (grid == 0) {
        cudaFuncSetAttribute(stream_kernel,
                             cudaFuncAttributeMaxDynamicSharedMemorySize,
                             SMEM_BYTES);
        int sms = 0;
        cudaDeviceGetAttribute(&sms, cudaDevAttrMultiProcessorCount, 0);
        grid = 2 * sms;   // 2 resident blocks per SM
    }

    select_kernel<<<NUM_GRAPHS, SEL_THREADS>>>(out, e);
    stream_kernel<<<grid, 1024, SMEM_BYTES>>>(
        (const float4*)x, e,
        (float4*)(out + X_OFF),
        (float4*)(out + EDGE_OFF),
        (float4*)(out + EDGE_OFF + NEDGE));
}

// round 16
// speedup vs baseline: 1.0574x; 1.0574x over previous
#include <cuda_runtime.h>
#include <stdint.h>

// Problem constants (fixed by the reference's setup_inputs)
#define NUM_GRAPHS 512
#define NPG        1024
#define KSEL       512
#define NTOT       (NUM_GRAPHS * NPG)     // 524288 nodes
#define NSEL       (NUM_GRAPHS * KSEL)    // 262144 selected
#define NEDGE      8388608                // 16 * NTOT

// Output layout (float32, concatenated reference outputs:
// x_sel [NSEL,64] | new_edge_index [2,NEDGE] | batch_sel [NSEL] | perm [NSEL])
#define X_OFF      0ll
#define EDGE_OFF   16777216ll             // NSEL * 64
#define BATCH_OFF  33554432ll             // EDGE_OFF + 2*NEDGE
#define PERM_OFF   33816576ll             // BATCH_OFF + NSEL

#define LUT_WORDS     (NTOT / 32)         // 16384
#define SMEM_BYTES    (LUT_WORDS * 4 + LUT_WORDS * 2)  // 96 KB

#define GATHER_CHUNKS 2048                // NSEL*8 threads / 1024
#define EDGE_CHUNKS   1024                // NEDGE/8 threads / 1024
#define TOTAL_CHUNKS  (GATHER_CHUNKS + EDGE_CHUNKS)

#define SEL_THREADS   512                 // select: 512 threads, 2 elems each

// Scratch (static device globals — no allocation)
__device__ int            g_perm[NSEL];
__device__ unsigned int   g_bits[LUT_WORDS];   // ballot word per 32 nodes
__device__ unsigned short g_base[LUT_WORDS];   // within-graph rank base (<=512)
__device__ int            g_is64;

__device__ __forceinline__ uint32_t rotl32(uint32_t x, int r) {
    return __funnelshift_l(x, x, r);
}

// Threefry-2x32, 20 rounds — bit-exact match of jax._src.prng.threefry2x32
__device__ __forceinline__ void threefry(uint32_t k0, uint32_t k1,
                                         uint32_t x0, uint32_t x1,
                                         uint32_t& o0, uint32_t& o1) {
    uint32_t k2 = k0 ^ k1 ^ 0x1BD11BDAu;
    x0 += k0; x1 += k1;
#define TF_R(r) { x0 += x1; x1 = rotl32(x1, (r)); x1 ^= x0; }
    TF_R(13) TF_R(15) TF_R(26) TF_R(6)   x0 += k1; x1 += k2 + 1u;
    TF_R(17) TF_R(29) TF_R(16) TF_R(24)  x0 += k2; x1 += k0 + 2u;
    TF_R(13) TF_R(15) TF_R(26) TF_R(6)   x0 += k0; x1 += k1 + 3u;
    TF_R(17) TF_R(29) TF_R(16) TF_R(24)  x0 += k1; x1 += k2 + 4u;
    TF_R(13) TF_R(15) TF_R(26) TF_R(6)   x0 += k2; x1 += k0 + 5u;
#undef TF_R
    o0 = x0; o1 = x1;
}

// One 512-thread block per graph, 2 elements per thread (e0=t, e1=t+512).
// Select = the 512 entries with smallest stable composite (key<<32|idx),
// via 1024-bucket radix select + exact tie resolution in the threshold
// bucket. Rank = prefix-popcount. 4 blocks/SM => single wave over 512 graphs.
__global__ __launch_bounds__(SEL_THREADS) void select_kernel(
    float* __restrict__ out, const unsigned int* __restrict__ e) {
    __shared__ unsigned int counts[1024];
    __shared__ unsigned int waux[32];
    __shared__ unsigned int woff[32];
    __shared__ unsigned int sThresh[2];       // [0]=T bucket, [1]=R
    __shared__ unsigned int sNT;
    __shared__ unsigned long long list[1024]; // threshold-bucket composites

    const int g = blockIdx.x;
    const int t = threadIdx.x;
    const int w = t >> 5;                     // 0..15
    const int lane = t & 31;

    // dtype sniff (int64 => odd 32-bit words all zero, ids < 2^19)
    if (g == 0 && w == 0) {
        unsigned int v = e[2 * lane + 1] | e[2 * (lane + 32) + 1];
        unsigned int any = __ballot_sync(0xFFFFFFFFu, v != 0u);
        if (lane == 0) g_is64 = (any == 0u) ? 1 : 0;
    }

    // Per-graph keys: key_g = threefry((0,42),(0,g)); subkey = threefry(key_g,(0,1))
    uint32_t a0, a1, b0, b1;
    threefry(0u, 42u, 0u, (uint32_t)g, a0, a1);
    threefry(a0, a1, 0u, 1u, b0, b1);

    const int eA = t;            // element 0
    const int eB = t + 512;      // element 1
    uint32_t cA0, cA1, cB0, cB1;
    threefry(b0, b1, 0u, (uint32_t)eA, cA0, cA1);
    threefry(b0, b1, 0u, (uint32_t)eB, cB0, cB1);
    const uint32_t skA = cA0 ^ cA1;
    const uint32_t skB = cB0 ^ cB1;
    const unsigned long long keyA =
        ((unsigned long long)skA << 32) | (unsigned long long)eA;
    const unsigned long long keyB =
        ((unsigned long long)skB << 32) | (unsigned long long)eB;
    const unsigned int bkA = skA >> 22;
    const unsigned int bkB = skB >> 22;

    counts[2 * t] = 0;
    counts[2 * t + 1] = 0;
    if (t == 0) sNT = 0;
    __syncthreads();
    atomicAdd(&counts[bkA], 1u);
    atomicAdd(&counts[bkB], 1u);
    __syncthreads();

    // Exclusive scan over counts[1024]: each thread owns pair (2t, 2t+1)
    {
        const unsigned int v0 = counts[2 * t];
        const unsigned int v1 = counts[2 * t + 1];
        const unsigned int s = v0 + v1;
        unsigned int inc = s;
#pragma unroll
        for (int d = 1; d < 32; d <<= 1) {
            unsigned int n_ = __shfl_up_sync(0xFFFFFFFFu, inc, d);
            if (lane >= d) inc += n_;
        }
        if (lane == 31) waux[w] = inc;        // 16 warp totals
        __syncthreads();
        if (w == 0 && lane < 16) {
            unsigned int sv = waux[lane];
            unsigned int si = sv;
#pragma unroll
            for (int d = 1; d < 16; d <<= 1) {
                unsigned int n_ = __shfl_up_sync(0x0000FFFFu, si, d);
                if (lane >= d) si += n_;
            }
            woff[lane] = si - sv;             // exclusive warp offsets
        }
        __syncthreads();
        const unsigned int exPair = woff[w] + inc - s;  // excl for 2t
        const unsigned int ex0 = exPair;
        const unsigned int ex1 = exPair + v0;
        if (ex0 <= 511u && 511u < ex0 + v0) {
            sThresh[0] = (unsigned int)(2 * t);
            sThresh[1] = 512u - ex0;
        }
        if (ex1 <= 511u && 511u < ex1 + v1) {
            sThresh[0] = (unsigned int)(2 * t + 1);
            sThresh[1] = 512u - ex1;
        }
    }
    __syncthreads();
    const unsigned int T = sThresh[0];
    const unsigned int R = sThresh[1];

    // Compact threshold-bucket composites, then exact rank-compare
    if (bkA == T) { unsigned int pos = atomicAdd(&sNT, 1u); list[pos] = keyA; }
    if (bkB == T) { unsigned int pos = atomicAdd(&sNT, 1u); list[pos] = keyB; }
    __syncthreads();
    const unsigned int nT = sNT;
    bool selA, selB;
    if (bkA < T) selA = true;
    else if (bkA > T) selA = false;
    else {
        unsigned int rank = 0;
        for (unsigned int jj = 0; jj < nT; jj++)
            rank += (list[jj] < keyA) ? 1u : 0u;
        selA = (rank < R);
    }
    if (bkB < T) selB = true;
    else if (bkB > T) selB = false;
    else {
        unsigned int rank = 0;
        for (unsigned int jj = 0; jj < nT; jj++)
            rank += (list[jj] < keyB) ? 1u : 0u;
        selB = (rank < R);
    }

    // Ballot ranks: element words — eA covers words [0,16), eB words [16,32)
    const unsigned int wordA = __ballot_sync(0xFFFFFFFFu, selA);
    const unsigned int wordB = __ballot_sync(0xFFFFFFFFu, selB);
    if (lane == 0) {
        waux[w] = __popc(wordA);
        waux[16 + w] = __popc(wordB);
    }
    __syncthreads();
    if (w == 0) {                              // scan all 32 word counts
        unsigned int sv = waux[lane];
        unsigned int si = sv;
#pragma unroll
        for (int d = 1; d < 32; d <<= 1) {
            unsigned int n_ = __shfl_up_sync(0xFFFFFFFFu, si, d);
            if (lane >= d) si += n_;
        }
        woff[lane] = si - sv;
    }
    __syncthreads();

    const unsigned int baseA = woff[w];        // within-graph, <=512
    const unsigned int baseB = woff[16 + w];
    if (lane == 0) {
        g_bits[g * 32 + w]      = wordA;
        g_base[g * 32 + w]      = (unsigned short)baseA;
        g_bits[g * 32 + 16 + w] = wordB;
        g_base[g * 32 + 16 + w] = (unsigned short)baseB;
    }
    if (selA) {
        const int rank = g * KSEL + (int)baseA + __popc(wordA & ((1u << lane) - 1u));
        const int global = g * NPG + eA;
        g_perm[rank] = global;
        out[BATCH_OFF + rank] = (float)g;
        out[PERM_OFF  + rank] = (float)global;
    }
    if (selB) {
        const int rank = g * KSEL + (int)baseB + __popc(wordB & ((1u << lane) - 1u));
        const int global = g * NPG + eB;
        g_perm[rank] = global;
        out[BATCH_OFF + rank] = (float)g;
        out[PERM_OFF  + rank] = (float)global;
    }
}

// Relabel node id via shared-memory packed LUT:
// global rank = (n>>10)*512 + base16[n>>5] + popc(bits & below-lane mask)
__device__ __forceinline__ int relabel_s(const unsigned int* __restrict__ sbits,
                                         const unsigned short* __restrict__ sbase,
                                         unsigned int n) {
    if (n >= NTOT) return -1;
    const unsigned int wi = n >> 5;
    const unsigned int W = sbits[wi];
    const unsigned int b = n & 31u;
    if (!((W >> b) & 1u)) return -1;
    return (int)((n >> 10) * KSEL + (unsigned int)sbase[wi]
                 + __popc(W & ((1u << b) - 1u)));
}

// Persistent stream kernel, 2 blocks/SM (96KB smem each): stage packed LUT,
// then grid-stride over 3072 chunks interleaved 2 gather : 1 edge.
// All streaming traffic uses .cs (evict-first). [R7/R11/R14 body — best measured]
__global__ __launch_bounds__(1024, 2) void stream_kernel(
    const float4* __restrict__ x,
    const unsigned int* __restrict__ eidx,
    float4* __restrict__ xout,
    float4* __restrict__ outr,
    float4* __restrict__ outc) {
    extern __shared__ unsigned int dyn[];
    unsigned int* sbits = dyn;                                  // 64 KB
    unsigned short* sbase = (unsigned short*)(dyn + LUT_WORDS); // 32 KB

    // Stage LUT (bits: 4096 uint4; base: 2048 uint4)
    {
        const uint4* src = (const uint4*)g_bits;
        uint4* dst = (uint4*)sbits;
#pragma unroll
        for (int k = 0; k < 4; k++)
            dst[k * 1024 + threadIdx.x] = __ldg(&src[k * 1024 + threadIdx.x]);
        const uint4* src2 = (const uint4*)g_base;
        uint4* dst2 = (uint4*)sbase;
#pragma unroll
        for (int k = 0; k < 2; k++)
            dst2[k * 1024 + threadIdx.x] = __ldg(&src2[k * 1024 + threadIdx.x]);
    }
    __syncthreads();

    const int tid = threadIdx.x;
    const bool is64 = (g_is64 != 0);

    for (unsigned int c = blockIdx.x; c < TOTAL_CHUNKS; c += gridDim.x) {
        const unsigned int phase = c % 3u;     // 0,1 => gather; 2 => edge
        if (phase != 2u) {
            const int gb = (int)(c / 3u) * 2 + (int)phase;   // 0..GATHER_CHUNKS-1
            const int i = gb * 1024 + tid;                   // 0 .. NSEL*8-1
            const int row = i >> 3;
            const int cc = i & 7;
            const long long src = (long long)__ldg(&g_perm[row]) * 16;
            const long long dst = (long long)row * 16;
            const float4 v0 = __ldcs(&x[src + cc]);
            const float4 v1 = __ldcs(&x[src + cc + 8]);
            __stcs(&xout[dst + cc],     v0);
            __stcs(&xout[dst + cc + 8], v1);
        } else {
            const int eb = (int)(c / 3u);                    // 0..EDGE_CHUNKS-1
            const int j = eb * 1024 + tid;
            const int e0 = j * 8;                            // 8 edges per thread
            int n[8], m[8];
            const int4* p = (const int4*)eidx;
            if (is64) {
                const int4* q = p + (NEDGE / 2);
                int4 A[4], B[4];
#pragma unroll
                for (int k = 0; k < 4; k++) {
                    A[k] = __ldcs(&p[e0 / 2 + k]);
                    B[k] = __ldcs(&q[e0 / 2 + k]);
                }
#pragma unroll
                for (int k = 0; k < 4; k++) {
                    n[2 * k] = A[k].x; n[2 * k + 1] = A[k].z;
                    m[2 * k] = B[k].x; m[2 * k + 1] = B[k].z;
                }
            } else {
                const int4* q = p + (NEDGE / 4);
                int4 A0 = __ldcs(&p[e0 / 4]), A1 = __ldcs(&p[e0 / 4 + 1]);
                int4 B0 = __ldcs(&q[e0 / 4]), B1 = __ldcs(&q[e0 / 4 + 1]);
                n[0] = A0.x; n[1] = A0.y; n[2] = A0.z; n[3] = A0.w;
                n[4] = A1.x; n[5] = A1.y; n[6] = A1.z; n[7] = A1.w;
                m[0] = B0.x; m[1] = B0.y; m[2] = B0.z; m[3] = B0.w;
                m[4] = B1.x; m[5] = B1.y; m[6] = B1.z; m[7] = B1.w;
            }
            float rr[8], cc2[8];
#pragma unroll
            for (int k = 0; k < 8; k++) {
                const int r  = relabel_s(sbits, sbase, (unsigned int)n[k]);
                const int cl = relabel_s(sbits, sbase, (unsigned int)m[k]);
                const bool keep = (r >= 0) & (cl >= 0);
                rr[k]  = keep ? (float)r  : -1.0f;
                cc2[k] = keep ? (float)cl : -1.0f;
            }
            __stcs(&outr[e0 / 4],     make_float4(rr[0], rr[1], rr[2], rr[3]));
            __stcs(&outr[e0 / 4 + 1], make_float4(rr[4], rr[5], rr[6], rr[7]));
            __stcs(&outc[e0 / 4],     make_float4(cc2[0], cc2[1], cc2[2], cc2[3]));
            __stcs(&outc[e0 / 4 + 1], make_float4(cc2[4], cc2[5], cc2[6], cc2[7]));
        }
    }
}

extern "C" void kernel_launch(void* const* d_in, const int* in_sizes, int n_in,
                              void* d_out, int out_size) {
    const float* x        = (const float*)d_in[0];
    const unsigned int* e = (const unsigned int*)d_in[1];
    float* out            = (float*)d_out;

    static int grid = 0;
    if (grid == 0) {
        cudaFuncSetAttribute(stream_kernel,
                             cudaFuncAttributeMaxDynamicSharedMemorySize,
                             SMEM_BYTES);
        int sms = 0;
        cudaDeviceGetAttribute(&sms, cudaDevAttrMultiProcessorCount, 0);
        grid = 2 * sms;   // 2 resident blocks per SM
    }

    select_kernel<<<NUM_GRAPHS, SEL_THREADS>>>(out, e);
    stream_kernel<<<grid, 1024, SMEM_BYTES>>>(
        (const float4*)x, e,
        (float4*)(out + X_OFF),
        (float4*)(out + EDGE_OFF),
        (float4*)(out + EDGE_OFF + NEDGE));
}